// round 1
// baseline (speedup 1.0000x reference)
#include <cuda_runtime.h>

#define NUM_GRAPHS 16384
#define EMB_DIM    128

// Scratch: per-graph start offsets (device globals — no allocation allowed).
__device__ int g_starts_atoms[NUM_GRAPHS + 1];
__device__ int g_starts_frags[NUM_GRAPHS + 1];
__device__ int g_is64_a;
__device__ int g_is64_f;

// ---------------------------------------------------------------------------
// Detect whether the index buffer is int64 or int32.
// Interpret as int64 and sample indices in [0, n/2) (always in-bounds for
// either dtype). If the true dtype is int32, samples away from the head
// combine two int32 values and blow past NUM_GRAPHS -> detected.
// ---------------------------------------------------------------------------
__global__ void detect_dtype_kernel(const void* idx, int n, int which) {
    if (threadIdx.x != 0 || blockIdx.x != 0) return;
    const long long* p64 = (const long long*)idx;
    int half = n / 2;                // safe upper bound in int64 elements
    if (half < 2) half = 2;
    bool ok64 = true;
    long long prev = -1;
    for (int k = 0; k < 16; ++k) {
        long long i = ((long long)k * (long long)(half - 1)) / 15;
        long long v = p64[i];
        if (v < prev || v < 0 || v >= NUM_GRAPHS) { ok64 = false; break; }
        prev = v;
    }
    if (which) g_is64_f = ok64 ? 1 : 0;
    else       g_is64_a = ok64 ? 1 : 0;
}

// ---------------------------------------------------------------------------
// Build starts[] from the sorted index array (boundary detection).
// starts[g] = first row with index == g (or first row with index > g if g
// is empty); starts[NUM_GRAPHS] = n.
// ---------------------------------------------------------------------------
__global__ void fill_starts_kernel(const void* idxp, int n, int which) {
    int* starts = which ? g_starts_frags : g_starts_atoms;
    int is64    = which ? g_is64_f       : g_is64_a;

    int i = blockIdx.x * blockDim.x + threadIdx.x;
    if (i >= n) return;

    int b, prev;
    if (is64) {
        const long long* p = (const long long*)idxp;
        b    = (int)p[i];
        prev = (i == 0) ? -1 : (int)p[i - 1];
    } else {
        const int* p = (const int*)idxp;
        b    = p[i];
        prev = (i == 0) ? -1 : p[i - 1];
    }
    for (int g = prev + 1; g <= b; ++g) starts[g] = i;
    if (i == n - 1) {
        for (int g = b + 1; g <= NUM_GRAPHS; ++g) starts[g] = n;
    }
}

// ---------------------------------------------------------------------------
// Segment sum: one CTA per (graph, half). 128 threads = 4 warps.
// Within a warp: lane l owns float4 columns [4l, 4l+4) -> one LDG.128 covers
// a full 128-float row per warp. Warps stride rows by 4; 4-deep unroll gives
// 16 outstanding 128b loads per CTA.
// ---------------------------------------------------------------------------
__device__ __forceinline__ float4 f4add(float4 a, float4 b) {
    a.x += b.x; a.y += b.y; a.z += b.z; a.w += b.w; return a;
}

__global__ __launch_bounds__(128) void segsum_kernel(
    const float4* __restrict__ xa,
    const float4* __restrict__ xf,
    float* __restrict__ out)
{
    int bid  = blockIdx.x;
    bool frag = bid >= NUM_GRAPHS;
    int gi   = frag ? bid - NUM_GRAPHS : bid;

    const int* starts = frag ? g_starts_frags : g_starts_atoms;
    const float4* x   = frag ? xf : xa;

    int s = starts[gi];
    int e = starts[gi + 1];

    int w    = threadIdx.x >> 5;
    int lane = threadIdx.x & 31;

    float4 a0 = make_float4(0.f, 0.f, 0.f, 0.f);
    float4 a1 = a0, a2 = a0, a3 = a0;

    int r = s + w;
    // 4-deep unroll: independent loads, DRAM latency hidden by MLP.
    for (; r + 12 < e; r += 16) {
        float4 v0 = __ldcs(&x[(size_t)(r     ) * 32 + lane]);
        float4 v1 = __ldcs(&x[(size_t)(r +  4) * 32 + lane]);
        float4 v2 = __ldcs(&x[(size_t)(r +  8) * 32 + lane]);
        float4 v3 = __ldcs(&x[(size_t)(r + 12) * 32 + lane]);
        a0 = f4add(a0, v0);
        a1 = f4add(a1, v1);
        a2 = f4add(a2, v2);
        a3 = f4add(a3, v3);
    }
    for (; r < e; r += 4) {
        a0 = f4add(a0, __ldcs(&x[(size_t)r * 32 + lane]));
    }
    a0 = f4add(f4add(a0, a1), f4add(a2, a3));

    // Cross-warp reduction (4 partial rows -> 1).
    __shared__ float4 sred[4][32];
    sred[w][lane] = a0;
    __syncthreads();

    if (w == 0) {
        float4 t = f4add(f4add(sred[0][lane], sred[1][lane]),
                         f4add(sred[2][lane], sred[3][lane]));
        size_t off = (size_t)gi * 256 + (frag ? 128 : 0) + (size_t)lane * 4;
        *(float4*)(out + off) = t;
    }
}

// ---------------------------------------------------------------------------
extern "C" void kernel_launch(void* const* d_in, const int* in_sizes, int n_in,
                              void* d_out, int out_size)
{
    const float4* xa   = (const float4*)d_in[0];
    const float4* xf   = (const float4*)d_in[1];
    const void*   ba   = d_in[2];
    const void*   bf   = d_in[3];
    float*        out  = (float*)d_out;

    int n_atoms = in_sizes[2];   // element count of batch == N_ATOMS
    int n_frags = in_sizes[3];   // element count of frag_batch == N_FRAGS

    detect_dtype_kernel<<<1, 32>>>(ba, n_atoms, 0);
    detect_dtype_kernel<<<1, 32>>>(bf, n_frags, 1);

    int tpb = 256;
    fill_starts_kernel<<<(n_atoms + tpb - 1) / tpb, tpb>>>(ba, n_atoms, 0);
    fill_starts_kernel<<<(n_frags + tpb - 1) / tpb, tpb>>>(bf, n_frags, 1);

    segsum_kernel<<<2 * NUM_GRAPHS, 128>>>(xa, xf, out);
    (void)n_in; (void)out_size;
}

// round 2
// speedup vs baseline: 1.0366x; 1.0366x over previous
#include <cuda_runtime.h>

#define NUM_GRAPHS 16384
#define EMB_DIM    128

// Scratch: per-graph start offsets (device globals — no allocation allowed).
__device__ int g_starts_atoms[NUM_GRAPHS + 1];
__device__ int g_starts_frags[NUM_GRAPHS + 1];

// ---------------------------------------------------------------------------
// Fused boundary-detection for BOTH index arrays in one launch.
//
// Dtype probe (int64 vs int32), done inline per-thread with one cached read:
// interpret the buffer as int64 and read element n/4. If the true dtype is
// int32, that word combines int32 elements n/2 and n/2+1; the high word is a
// sorted graph id around NUM_GRAPHS/2 (nonzero mid-array), so the value is
// >= 2^32. If the true dtype is int64 it is a valid id in [0, NUM_GRAPHS).
//
// starts[g] = first row whose index == g (empty graphs inherit the next
// nonempty graph's start); starts[NUM_GRAPHS] = n.
// ---------------------------------------------------------------------------
__global__ void fill_starts_fused_kernel(const void* idx_a, int n_a,
                                         const void* idx_f, int n_f,
                                         int nblk_a)
{
    bool frag = (int)blockIdx.x >= nblk_a;
    const void* idxp = frag ? idx_f : idx_a;
    int         n    = frag ? n_f   : n_a;
    int*        starts = frag ? g_starts_frags : g_starts_atoms;
    int blk = frag ? (blockIdx.x - nblk_a) : blockIdx.x;

    int i = blk * blockDim.x + threadIdx.x;
    if (i >= n) return;

    const long long* p64 = (const long long*)idxp;
    long long probe = p64[n / 4];
    bool is64 = (probe >= 0 && probe < NUM_GRAPHS);

    int b, prev;
    if (is64) {
        b    = (int)p64[i];
        prev = (i == 0) ? -1 : (int)p64[i - 1];
    } else {
        const int* p = (const int*)idxp;
        b    = p[i];
        prev = (i == 0) ? -1 : p[i - 1];
    }
    for (int g = prev + 1; g <= b; ++g) starts[g] = i;
    if (i == n - 1) {
        for (int g = b + 1; g <= NUM_GRAPHS; ++g) starts[g] = n;
    }
}

// ---------------------------------------------------------------------------
// Segment sum: one CTA per (graph, half). 128 threads = 4 warps.
// Within a warp: lane l owns float4 columns [4l, 4l+4) -> one warp's LDG.128s
// cover a full 128-float row (512B, 4 consecutive 128B lines). Warps stride
// rows by 4; 4-deep unroll gives 16 outstanding 128b loads per CTA.
// ---------------------------------------------------------------------------
__device__ __forceinline__ float4 f4add(float4 a, float4 b) {
    a.x += b.x; a.y += b.y; a.z += b.z; a.w += b.w; return a;
}

__global__ __launch_bounds__(128) void segsum_kernel(
    const float4* __restrict__ xa,
    const float4* __restrict__ xf,
    float* __restrict__ out)
{
    int bid  = blockIdx.x;
    bool frag = bid >= NUM_GRAPHS;
    int gi   = frag ? bid - NUM_GRAPHS : bid;

    const int* starts = frag ? g_starts_frags : g_starts_atoms;
    const float4* x   = frag ? xf : xa;

    int s = starts[gi];
    int e = starts[gi + 1];

    int w    = threadIdx.x >> 5;
    int lane = threadIdx.x & 31;

    float4 a0 = make_float4(0.f, 0.f, 0.f, 0.f);
    float4 a1 = a0, a2 = a0, a3 = a0;

    int r = s + w;
    // 4-deep unroll: independent loads, DRAM latency hidden by MLP.
    for (; r + 12 < e; r += 16) {
        float4 v0 = __ldcs(&x[(size_t)(r     ) * 32 + lane]);
        float4 v1 = __ldcs(&x[(size_t)(r +  4) * 32 + lane]);
        float4 v2 = __ldcs(&x[(size_t)(r +  8) * 32 + lane]);
        float4 v3 = __ldcs(&x[(size_t)(r + 12) * 32 + lane]);
        a0 = f4add(a0, v0);
        a1 = f4add(a1, v1);
        a2 = f4add(a2, v2);
        a3 = f4add(a3, v3);
    }
    for (; r < e; r += 4) {
        a0 = f4add(a0, __ldcs(&x[(size_t)r * 32 + lane]));
    }
    a0 = f4add(f4add(a0, a1), f4add(a2, a3));

    // Cross-warp reduction (4 partial rows -> 1).
    __shared__ float4 sred[4][32];
    sred[w][lane] = a0;
    __syncthreads();

    if (w == 0) {
        float4 t = f4add(f4add(sred[0][lane], sred[1][lane]),
                         f4add(sred[2][lane], sred[3][lane]));
        size_t off = (size_t)gi * 256 + (frag ? 128 : 0) + (size_t)lane * 4;
        *(float4*)(out + off) = t;
    }
}

// ---------------------------------------------------------------------------
extern "C" void kernel_launch(void* const* d_in, const int* in_sizes, int n_in,
                              void* d_out, int out_size)
{
    const float4* xa   = (const float4*)d_in[0];
    const float4* xf   = (const float4*)d_in[1];
    const void*   ba   = d_in[2];
    const void*   bf   = d_in[3];
    float*        out  = (float*)d_out;

    int n_atoms = in_sizes[2];   // element count of batch == N_ATOMS
    int n_frags = in_sizes[3];   // element count of frag_batch == N_FRAGS

    const int tpb = 256;
    int nblk_a = (n_atoms + tpb - 1) / tpb;
    int nblk_f = (n_frags + tpb - 1) / tpb;
    fill_starts_fused_kernel<<<nblk_a + nblk_f, tpb>>>(ba, n_atoms, bf, n_frags, nblk_a);

    segsum_kernel<<<2 * NUM_GRAPHS, 128>>>(xa, xf, out);
    (void)n_in; (void)out_size;
}